// round 2
// baseline (speedup 1.0000x reference)
#include <cuda_runtime.h>

// SSIM loss, fully fused single pass + tiny reduce kernel.
// img1, img2: [32,3,512,512] fp32. Output: scalar fp32 = 1 - mean(ssim_map).

#define HW       512
#define NPLANES  96          // 32*3
#define BAND     66          // rows per block (multiple of 11!)
#define NBANDS   8           // 8*66 = 528 >= 512
#define VB       528         // padded smem row width (>= 512+10)

namespace {
// exp(-k^2 / (2*1.5^2)) for k = 5..0 (unnormalized), normalized at compile time.
constexpr double G_[6] = {0.0038659201595884,   // exp(-50/9)
                          0.0285655007845504,   // exp(-32/9)
                          0.1353352832366127,   // exp(-2)
                          0.4111122905071874,   // exp(-8/9)
                          0.8007374029168081,   // exp(-2/9)
                          1.0};
constexpr double GSUM = 2.0*(G_[0]+G_[1]+G_[2]+G_[3]+G_[4]) + 1.0;
constexpr float gwf(int j){ return (float)(G_[j < 6 ? j : 10 - j] / GSUM); }
}

__device__ constexpr float GW[11] = {
    gwf(0), gwf(1), gwf(2), gwf(3), gwf(4), gwf(5),
    gwf(6), gwf(7), gwf(8), gwf(9), gwf(10)};

__device__ float g_part[NPLANES * NBANDS];

// Ingest one raw input row into the 11-phase vertical accumulator pipeline.
// Deposit with index j goes to slot (PH + j + 6) % 11 and corresponds to
// output row o = r + j - 5 (weights symmetric, so GW[j] is the right weight).
// JMIN masks deposits so only outputs o >= o0 receive contributions
// (prologue rows must not contaminate slots with previous-band outputs).
template<int PH, int JMIN>
__device__ __forceinline__ void ingest(float (&A)[5][11], float v1, float v2)
{
    const float q2 = v1 * v1;
    const float q3 = v2 * v2;
    const float q4 = v1 * v2;
#pragma unroll
    for (int j = JMIN; j < 11; ++j) {
        const int   s = (PH + j + 6) % 11;
        const float w = GW[j];
        A[0][s] = fmaf(w, v1, A[0][s]);
        A[1][s] = fmaf(w, v2, A[1][s]);
        A[2][s] = fmaf(w, q2, A[2][s]);
        A[3][s] = fmaf(w, q3, A[3][s]);
        A[4][s] = fmaf(w, q4, A[4][s]);
    }
}

// One steady-state row step: prefetch row o+6, ingest row o+5 (held in cv),
// emit vertical results for row o to smem, sync, horizontal conv + SSIM.
template<int PHI>
__device__ __forceinline__ void step(float (&A)[5][11], int o, int buf,
                                     const float* __restrict__ p1,
                                     const float* __restrict__ p2, int c,
                                     float (&vbuf)[2][5][VB],
                                     float& cv1, float& cv2, float& lsum)
{
    // prefetch next input row (consumed next step)
    const int  rn = o + 6;
    const bool ok = rn < HW;
    const float nv1 = ok ? __ldg(&p1[(size_t)rn * HW + c]) : 0.f;
    const float nv2 = ok ? __ldg(&p2[(size_t)rn * HW + c]) : 0.f;

    ingest<(PHI + 5) % 11, 0>(A, cv1, cv2);
    cv1 = nv1; cv2 = nv2;

    // emit vertical conv results for output row o (slot PHI complete)
#pragma unroll
    for (int p = 0; p < 5; ++p) {
        vbuf[buf][p][c + 5] = A[p][PHI];
        A[p][PHI] = 0.f;
    }
    __syncthreads();

    // horizontal conv over the 5 vertical planes
    float m1 = 0.f, m2 = 0.f, s11 = 0.f, s22 = 0.f, s12 = 0.f;
#pragma unroll
    for (int k = 0; k < 11; ++k) {
        const float w = GW[k];
        m1  = fmaf(w, vbuf[buf][0][c + k], m1);
        m2  = fmaf(w, vbuf[buf][1][c + k], m2);
        s11 = fmaf(w, vbuf[buf][2][c + k], s11);
        s22 = fmaf(w, vbuf[buf][3][c + k], s22);
        s12 = fmaf(w, vbuf[buf][4][c + k], s12);
    }

    const float C1 = 1e-4f, C2 = 9e-4f;
    const float mu12 = m1 * m2;
    const float m1s  = m1 * m1;
    const float m2s  = m2 * m2;
    const float Anum = 2.f * mu12 + C1;
    const float Bnum = 2.f * (s12 - mu12) + C2;
    const float Cden = m1s + m2s + C1;
    const float Dden = (s11 - m1s) + (s22 - m2s) + C2;
    const float ssim = __fdividef(Anum * Bnum, Cden * Dden);
    if (o < HW) lsum += ssim;
}

__global__ __launch_bounds__(512, 1)
void ssim_main(const float* __restrict__ img1, const float* __restrict__ img2)
{
    const int c     = threadIdx.x;          // column 0..511
    const int band  = blockIdx.x;           // 0..7
    const int plane = blockIdx.y;           // 0..95
    const int o0    = band * BAND;          // o0 % 11 == 0 (BAND = 66)
    const float* __restrict__ p1 = img1 + (size_t)plane * HW * HW;
    const float* __restrict__ p2 = img2 + (size_t)plane * HW * HW;

    __shared__ float vbuf[2][5][VB];
    __shared__ float red[512];

    // zero-pad vbuf borders (columns <0 and >=512 of the image; never rewritten)
#pragma unroll
    for (int b = 0; b < 2; ++b)
#pragma unroll
        for (int p = 0; p < 5; ++p) {
            if (c < 5)   vbuf[b][p][c] = 0.f;
            if (c >= 501) vbuf[b][p][c + 16] = 0.f;   // 517..527
        }

    float acc[5][11];
#pragma unroll
    for (int p = 0; p < 5; ++p)
#pragma unroll
        for (int j = 0; j < 11; ++j) acc[p][j] = 0.f;

    __syncthreads();

    // prefetch first input row (o0-5)
    float cv1, cv2;
    {
        const int  r  = o0 - 5;
        const bool ok = (unsigned)r < (unsigned)HW;
        cv1 = ok ? __ldg(&p1[(size_t)r * HW + c]) : 0.f;
        cv2 = ok ? __ldg(&p2[(size_t)r * HW + c]) : 0.f;
    }

    // prologue: ingest rows o0-5 .. o0+4 (phase (i+6)%11, static).
    // JMIN = 10 - i restricts deposits to outputs o >= o0: deposit index j
    // of row r corresponds to output o = r + j - 5, and r = o0 - 5 + i.
#define PROLOG(i) {                                                     \
        const int  rn_ = o0 - 4 + (i);                                  \
        const bool ok_ = (unsigned)rn_ < (unsigned)HW;                  \
        const float nv1_ = ok_ ? __ldg(&p1[(size_t)rn_ * HW + c]) : 0.f;\
        const float nv2_ = ok_ ? __ldg(&p2[(size_t)rn_ * HW + c]) : 0.f;\
        ingest<((i) + 6) % 11, 10 - (i)>(acc, cv1, cv2);                \
        cv1 = nv1_; cv2 = nv2_; }
    PROLOG(0) PROLOG(1) PROLOG(2) PROLOG(3) PROLOG(4)
    PROLOG(5) PROLOG(6) PROLOG(7) PROLOG(8) PROLOG(9)
#undef PROLOG

    float lsum = 0.f;
    int t = 0;
#define STEP(PHI) { step<PHI>(acc, o0 + t, t & 1, p1, p2, c, vbuf, cv1, cv2, lsum); ++t; }
#pragma unroll 1
    for (int blk = 0; blk < 6; ++blk) {   // 6 * 11 = 66 output rows
        STEP(0) STEP(1) STEP(2) STEP(3) STEP(4) STEP(5)
        STEP(6) STEP(7) STEP(8) STEP(9) STEP(10)
    }
#undef STEP

    // block reduction (deterministic)
    red[c] = lsum;
    __syncthreads();
#pragma unroll
    for (int s = 256; s > 0; s >>= 1) {
        if (c < s) red[c] += red[c + s];
        __syncthreads();
    }
    if (c == 0) g_part[plane * NBANDS + band] = red[0];
}

__global__ void ssim_reduce(float* __restrict__ out)
{
    __shared__ double sd[256];
    const int t = threadIdx.x;
    double s = 0.0;
    for (int i = t; i < NPLANES * NBANDS; i += 256) s += (double)g_part[i];
    sd[t] = s;
    __syncthreads();
#pragma unroll
    for (int k = 128; k > 0; k >>= 1) {
        if (t < k) sd[t] += sd[t + k];
        __syncthreads();
    }
    if (t == 0) out[0] = (float)(1.0 - sd[0] / 25165824.0);  // 32*3*512*512
}

extern "C" void kernel_launch(void* const* d_in, const int* in_sizes, int n_in,
                              void* d_out, int out_size)
{
    (void)in_sizes; (void)n_in; (void)out_size;
    const float* img1 = (const float*)d_in[0];
    const float* img2 = (const float*)d_in[1];
    dim3 grid(NBANDS, NPLANES);
    ssim_main<<<grid, 512>>>(img1, img2);
    ssim_reduce<<<1, 256>>>((float*)d_out);
}

// round 3
// speedup vs baseline: 1.7046x; 1.7046x over previous
#include <cuda_runtime.h>

// SSIM loss, fused single pass + tiny reduce kernel.
// img1, img2: [32,3,512,512] fp32. Output: scalar fp32 = 1 - mean(ssim_map).
//
// Per block: one (plane, 44-row band). 512 threads.
// Vertical 11-tap conv via 11-phase register accumulator ring (1 col/thread),
// emitting 4 rows at a time into a 4-row smem staging buffer; horizontal
// 11-tap conv + SSIM map computed 4 px/thread with LDS.128 loads.

#define HW       512
#define NPLANES  96          // 32*3
#define BAND     44          // rows per block (lcm(4,11) keeps phases static)
#define NBANDS   12          // 12*44 = 528 >= 512
#define VB       528         // padded staging row width (>= 512+16 read span)

namespace {
constexpr double G_[6] = {0.0038659201595884,   // exp(-50/9)
                          0.0285655007845504,   // exp(-32/9)
                          0.1353352832366127,   // exp(-2)
                          0.4111122905071874,   // exp(-8/9)
                          0.8007374029168081,   // exp(-2/9)
                          1.0};
constexpr double GSUM = 2.0*(G_[0]+G_[1]+G_[2]+G_[3]+G_[4]) + 1.0;
constexpr float gwf(int j){ return (float)(G_[j < 6 ? j : 10 - j] / GSUM); }
}

__device__ constexpr float GW[11] = {
    gwf(0), gwf(1), gwf(2), gwf(3), gwf(4), gwf(5),
    gwf(6), gwf(7), gwf(8), gwf(9), gwf(10)};

__device__ float g_part[NPLANES * NBANDS];

// Deposit j of an ingested row (pipeline phase PH) goes to ring slot
// (PH + j + 6) % 11 and belongs to output row o = r + j - 5.
// JMIN masks prologue deposits so only outputs o >= o0 receive contributions.
template<int PH, int JMIN>
__device__ __forceinline__ void ingest(float (&A)[5][11], float v1, float v2)
{
    const float q2 = v1 * v1;
    const float q3 = v2 * v2;
    const float q4 = v1 * v2;
#pragma unroll
    for (int j = JMIN; j < 11; ++j) {
        const int   s = (PH + j + 6) % 11;
        const float w = GW[j];
        A[0][s] = fmaf(w, v1, A[0][s]);
        A[1][s] = fmaf(w, v2, A[1][s]);
        A[2][s] = fmaf(w, q2, A[2][s]);
        A[3][s] = fmaf(w, q3, A[3][s]);
        A[4][s] = fmaf(w, q4, A[4][s]);
    }
}

__global__ __launch_bounds__(512, 1)
void ssim_main(const float* __restrict__ img1, const float* __restrict__ img2)
{
    const int c     = threadIdx.x;          // column 0..511 (vertical pass)
    const int band  = blockIdx.x;           // 0..11
    const int plane = blockIdx.y;           // 0..95
    const int o0    = band * BAND;
    const float* __restrict__ p1 = img1 + (size_t)plane * HW * HW;
    const float* __restrict__ p2 = img2 + (size_t)plane * HW * HW;

    // staging: 5 planes x 4 rows x VB floats, float4-aligned for LDS.128
    __shared__ float4 vb4[5][4][VB / 4];
    __shared__ float  red[512];

    // zero-pad column borders (buffer idx [0,4] and [517,527]); emissions
    // only touch [5,516], so one-time init suffices for all groups.
#pragma unroll
    for (int p = 0; p < 5; ++p)
#pragma unroll
        for (int s = 0; s < 4; ++s) {
            float* b = (float*)vb4[p][s];
            if (c < 5)    b[c] = 0.f;
            if (c >= 501) b[c + 16] = 0.f;   // 517..527
        }

    float acc[5][11];
#pragma unroll
    for (int p = 0; p < 5; ++p)
#pragma unroll
        for (int j = 0; j < 11; ++j) acc[p][j] = 0.f;

    __syncthreads();

    // prefetch first input row (o0-5)
    float cv1, cv2;
    {
        const int  r  = o0 - 5;
        const bool ok = (unsigned)r < (unsigned)HW;
        cv1 = ok ? __ldg(&p1[(size_t)r * HW + c]) : 0.f;
        cv2 = ok ? __ldg(&p2[(size_t)r * HW + c]) : 0.f;
    }

    // prologue: ingest rows o0-5 .. o0+4 with JMIN = 10 - i masking
#define PROLOG(i) {                                                     \
        const int  rn_ = o0 - 4 + (i);                                  \
        const bool ok_ = (unsigned)rn_ < (unsigned)HW;                  \
        const float nv1_ = ok_ ? __ldg(&p1[(size_t)rn_ * HW + c]) : 0.f;\
        const float nv2_ = ok_ ? __ldg(&p2[(size_t)rn_ * HW + c]) : 0.f;\
        ingest<((i) + 6) % 11, 10 - (i)>(acc, cv1, cv2);                \
        cv1 = nv1_; cv2 = nv2_; }
    PROLOG(0) PROLOG(1) PROLOG(2) PROLOG(3) PROLOG(4)
    PROLOG(5) PROLOG(6) PROLOG(7) PROLOG(8) PROLOG(9)
#undef PROLOG

    float lsum = 0.f;
    const int rr = c >> 7;            // horizontal: my row within group
    const int cb = (c & 127) << 2;    // horizontal: my 4-col base

    // Vertical step T (0..43): ingest row o0+T+5 (phase (T+5)%11, matching
    // the prologue chain), emit output row o0+T from slot T%11 into staging
    // sub-row T&3, prefetch row o0+T+6.
#define VSTEP(T) {                                                          \
        const int  rn_ = o0 + (T) + 6;                                      \
        const bool ok_ = rn_ < HW;                                          \
        const float nv1_ = ok_ ? __ldg(&p1[(size_t)rn_ * HW + c]) : 0.f;    \
        const float nv2_ = ok_ ? __ldg(&p2[(size_t)rn_ * HW + c]) : 0.f;    \
        ingest<((T) + 5) % 11, 0>(acc, cv1, cv2);                           \
        cv1 = nv1_; cv2 = nv2_;                                             \
        _Pragma("unroll")                                                   \
        for (int p = 0; p < 5; ++p) {                                       \
            ((float*)vb4[p][(T) & 3])[c + 5] = acc[p][(T) % 11];            \
            acc[p][(T) % 11] = 0.f;                                         \
        } }

    // Horizontal + SSIM for group G (output rows o0+4G .. o0+4G+3).
    // Output col cc uses staging indices [cc .. cc+10]; 4 outputs read
    // [cb .. cb+13], fetched as 4 aligned float4 per plane.
#define HSTEP(G) {                                                          \
        __syncthreads();                                                    \
        float r[5][4];                                                      \
        _Pragma("unroll")                                                   \
        for (int p = 0; p < 5; ++p) {                                       \
            const float4* q = &vb4[p][rr][cb >> 2];                         \
            const float4 A = q[0], B = q[1], Cc = q[2], D = q[3];           \
            const float v[16] = {A.x, A.y, A.z, A.w,  B.x, B.y, B.z, B.w,   \
                                 Cc.x, Cc.y, Cc.z, Cc.w,  D.x, D.y, D.z, D.w}; \
            _Pragma("unroll")                                               \
            for (int i = 0; i < 4; ++i) {                                   \
                float s = 0.f;                                              \
                _Pragma("unroll")                                           \
                for (int k = 0; k < 11; ++k) s = fmaf(GW[k], v[i + k], s);  \
                r[p][i] = s;                                                \
            }                                                               \
        }                                                                   \
        const int o = o0 + 4 * (G) + rr;                                    \
        if (o < HW) {                                                       \
            _Pragma("unroll")                                               \
            for (int i = 0; i < 4; ++i) {                                   \
                const float C1 = 1e-4f, C2 = 9e-4f;                         \
                const float m1 = r[0][i], m2 = r[1][i];                     \
                const float mu12 = m1 * m2;                                 \
                const float m1s  = m1 * m1;                                 \
                const float m2s  = m2 * m2;                                 \
                const float Anum = 2.f * mu12 + C1;                         \
                const float Bnum = 2.f * (r[4][i] - mu12) + C2;             \
                const float Cden = m1s + m2s + C1;                          \
                const float Dden = (r[2][i] - m1s) + (r[3][i] - m2s) + C2;  \
                lsum += __fdividef(Anum * Bnum, Cden * Dden);               \
            }                                                               \
        }                                                                   \
        __syncthreads(); }

#define GROUP(G) VSTEP(4*(G)) VSTEP(4*(G)+1) VSTEP(4*(G)+2) VSTEP(4*(G)+3) HSTEP(G)
    GROUP(0) GROUP(1) GROUP(2) GROUP(3) GROUP(4) GROUP(5)
    GROUP(6) GROUP(7) GROUP(8) GROUP(9) GROUP(10)
#undef GROUP
#undef VSTEP
#undef HSTEP

    // deterministic block reduction
    red[c] = lsum;
    __syncthreads();
#pragma unroll
    for (int s = 256; s > 0; s >>= 1) {
        if (c < s) red[c] += red[c + s];
        __syncthreads();
    }
    if (c == 0) g_part[plane * NBANDS + band] = red[0];
}

__global__ void ssim_reduce(float* __restrict__ out)
{
    __shared__ double sd[256];
    const int t = threadIdx.x;
    double s = 0.0;
    for (int i = t; i < NPLANES * NBANDS; i += 256) s += (double)g_part[i];
    sd[t] = s;
    __syncthreads();
#pragma unroll
    for (int k = 128; k > 0; k >>= 1) {
        if (t < k) sd[t] += sd[t + k];
        __syncthreads();
    }
    if (t == 0) out[0] = (float)(1.0 - sd[0] / 25165824.0);  // 32*3*512*512
}

extern "C" void kernel_launch(void* const* d_in, const int* in_sizes, int n_in,
                              void* d_out, int out_size)
{
    (void)in_sizes; (void)n_in; (void)out_size;
    const float* img1 = (const float*)d_in[0];
    const float* img2 = (const float*)d_in[1];
    dim3 grid(NBANDS, NPLANES);
    ssim_main<<<grid, 512>>>(img1, img2);
    ssim_reduce<<<1, 256>>>((float*)d_out);
}

// round 4
// speedup vs baseline: 1.7303x; 1.0150x over previous
#include <cuda_runtime.h>

// SSIM loss, fully fused: one main kernel (incl. final reduction).
// img1, img2: [32,3,512,512] fp32. Output: scalar fp32 = 1 - mean(ssim_map).
//
// Per block: one (plane, 44-row band), 512 threads.
// Vertical 11-tap conv via 11-phase register accumulator ring (1 col/thread),
// emitting 4-row groups into a DOUBLE-BUFFERED smem staging area; horizontal
// 11-tap conv + SSIM computed 4 px/thread with LDS.128. One sync per group.
// Next group's input rows are prefetched a full group ahead (MLP=8).

#define HW       512
#define NPLANES  96            // 32*3
#define BAND     44            // rows per block
#define NBANDS   12            // 12*44 = 528 >= 512
#define NBLK     (NBANDS * NPLANES)   // 1152
#define VB       528           // padded staging row width
#define VB4      (VB / 4)
#define SMEM_DYN (2 * 5 * 4 * VB4 * 16)   // 84480 bytes

namespace {
constexpr double G_[6] = {0.0038659201595884,   // exp(-50/9)
                          0.0285655007845504,   // exp(-32/9)
                          0.1353352832366127,   // exp(-2)
                          0.4111122905071874,   // exp(-8/9)
                          0.8007374029168081,   // exp(-2/9)
                          1.0};
constexpr double GSUM = 2.0*(G_[0]+G_[1]+G_[2]+G_[3]+G_[4]) + 1.0;
constexpr float gwf(int j){ return (float)(G_[j < 6 ? j : 10 - j] / GSUM); }
}

__device__ constexpr float GW[11] = {
    gwf(0), gwf(1), gwf(2), gwf(3), gwf(4), gwf(5),
    gwf(6), gwf(7), gwf(8), gwf(9), gwf(10)};

__device__ float    g_part[NBLK];
__device__ unsigned g_count = 0;

// Deposit j of an ingested row (ring phase PH) goes to slot (PH+j+6)%11 and
// belongs to output row o = r + j - 5. JMIN masks prologue deposits so only
// outputs o >= o0 receive contributions.
template<int PH, int JMIN>
__device__ __forceinline__ void ingest(float (&A)[5][11], float v1, float v2)
{
    const float q2 = v1 * v1;
    const float q3 = v2 * v2;
    const float q4 = v1 * v2;
#pragma unroll
    for (int j = JMIN; j < 11; ++j) {
        const int   s = (PH + j + 6) % 11;
        const float w = GW[j];
        A[0][s] = fmaf(w, v1, A[0][s]);
        A[1][s] = fmaf(w, v2, A[1][s]);
        A[2][s] = fmaf(w, q2, A[2][s]);
        A[3][s] = fmaf(w, q3, A[3][s]);
        A[4][s] = fmaf(w, q4, A[4][s]);
    }
}

__global__ __launch_bounds__(512, 1)
void ssim_main(const float* __restrict__ img1, const float* __restrict__ img2,
               float* __restrict__ out)
{
    extern __shared__ float4 dynbuf[];   // [2][5][4][VB4]
#define VBUF(B, P, S) ((float*)(dynbuf + (((B)*5 + (P))*4 + (S)) * VB4))

    const int c     = threadIdx.x;          // column 0..511 (vertical pass)
    const int band  = blockIdx.x;           // 0..11
    const int plane = blockIdx.y;           // 0..95
    const int o0    = band * BAND;
    const float* __restrict__ p1 = img1 + (size_t)plane * HW * HW;
    const float* __restrict__ p2 = img2 + (size_t)plane * HW * HW;

    __shared__ float  red[16];
    __shared__ double sd[512];
    __shared__ int    amLast;

    // one-time zero of column borders (emits only touch [5,516])
#pragma unroll
    for (int b = 0; b < 2; ++b)
#pragma unroll
        for (int p = 0; p < 5; ++p)
#pragma unroll
            for (int s = 0; s < 4; ++s) {
                float* bb = VBUF(b, p, s);
                if (c < 5)    bb[c] = 0.f;
                if (c >= 501) bb[c + 16] = 0.f;   // 517..527
            }

    float acc[5][11];
#pragma unroll
    for (int p = 0; p < 5; ++p)
#pragma unroll
        for (int j = 0; j < 11; ++j) acc[p][j] = 0.f;

    __syncthreads();

    // ── prologue: ingest rows o0-5 .. o0+4 with JMIN = 10-i masking ──
    // (row o0-5+i has ring phase (6+i)%11; straight-line → ptxas hoists LDGs)
#define PROLOG(i) {                                                          \
        const int  r_  = o0 - 5 + (i);                                       \
        const bool ok_ = (unsigned)r_ < (unsigned)HW;                        \
        const float v1_ = ok_ ? __ldg(&p1[(size_t)r_ * HW + c]) : 0.f;       \
        const float v2_ = ok_ ? __ldg(&p2[(size_t)r_ * HW + c]) : 0.f;       \
        ingest<((i) + 6) % 11, 10 - (i)>(acc, v1_, v2_); }
    PROLOG(0) PROLOG(1) PROLOG(2) PROLOG(3) PROLOG(4)
    PROLOG(5) PROLOG(6) PROLOG(7) PROLOG(8) PROLOG(9)
#undef PROLOG

    // prefetch register banks: bank (G+1)&1 loads ingest rows for group G+1
    float nv1[2][4], nv2[2][4];
#define LOADS(G) {                                                           \
        _Pragma("unroll")                                                    \
        for (int i = 0; i < 4; ++i) {                                        \
            const int  r_  = o0 + 4 * (G) + 9 + i;                           \
            const bool ok_ = r_ < HW;                                        \
            nv1[((G) + 1) & 1][i] = ok_ ? __ldg(&p1[(size_t)r_ * HW + c]) : 0.f; \
            nv2[((G) + 1) & 1][i] = ok_ ? __ldg(&p2[(size_t)r_ * HW + c]) : 0.f; \
        } }

    // ingest + emit one row of group G (sub-row i): row o0+4G+5+i,
    // ring phase (4G+i+5)%11, output slot (4G+i)%11, buffer G&1
#define ING(G, i) {                                                          \
        ingest<((4 * (G) + (i)) + 5) % 11, 0>(acc, nv1[(G) & 1][(i)],        \
                                              nv2[(G) & 1][(i)]);            \
        _Pragma("unroll")                                                    \
        for (int p = 0; p < 5; ++p) {                                        \
            VBUF((G) & 1, p, (i))[c + 5] = acc[p][(4 * (G) + (i)) % 11];     \
            acc[p][(4 * (G) + (i)) % 11] = 0.f;                              \
        } }

    float lsum = 0.f;
    const int rr = c >> 7;            // horizontal: my row within group
    const int cq = c & 127;           // horizontal: my float4 base index

    // horizontal conv + SSIM for group G out of buffer B (no syncs inside)
#define HSTEP(G, B) {                                                        \
        float hr[5][4];                                                      \
        _Pragma("unroll")                                                    \
        for (int p = 0; p < 5; ++p) {                                        \
            const float4* q = dynbuf + (((B)*5 + p)*4 + rr) * VB4 + cq;      \
            const float4 A = q[0], Bv = q[1], Cv = q[2], D = q[3];           \
            const float v[16] = {A.x, A.y, A.z, A.w,  Bv.x, Bv.y, Bv.z, Bv.w,\
                                 Cv.x, Cv.y, Cv.z, Cv.w,  D.x, D.y, D.z, D.w};\
            _Pragma("unroll")                                                \
            for (int i = 0; i < 4; ++i) {                                    \
                float s = 0.f;                                               \
                _Pragma("unroll")                                            \
                for (int k = 0; k < 11; ++k) s = fmaf(GW[k], v[i + k], s);   \
                hr[p][i] = s;                                                \
            }                                                                \
        }                                                                    \
        const int o = o0 + 4 * (G) + rr;                                     \
        if (o < HW) {                                                        \
            _Pragma("unroll")                                                \
            for (int i = 0; i < 4; ++i) {                                    \
                const float C1 = 1e-4f, C2 = 9e-4f;                          \
                const float m1 = hr[0][i], m2 = hr[1][i];                    \
                const float mu12 = m1 * m2;                                  \
                const float m1s  = m1 * m1;                                  \
                const float m2s  = m2 * m2;                                  \
                const float Anum = 2.f * mu12 + C1;                          \
                const float Bnum = 2.f * (hr[4][i] - mu12) + C2;             \
                const float Cden = m1s + m2s + C1;                           \
                const float Dden = (hr[2][i] - m1s) + (hr[3][i] - m2s) + C2; \
                lsum += __fdividef(Anum * Bnum, Cden * Dden);                \
            }                                                                \
        } }

    // bank 0 <- ingest rows of group 0 (o0+5..o0+8)
    LOADS(-1)
    // group 0: prefetch group-1 rows, ingest bank 0, emit buf 0
    LOADS(0)
    ING(0, 0) ING(0, 1) ING(0, 2) ING(0, 3)

    // groups 1..10: sync; prefetch G+1; horizontal of G-1; vertical of G
#define GBODY(G) {                                                           \
        __syncthreads();                                                     \
        if ((G) < 10) { LOADS(G) }                                           \
        HSTEP((G) - 1, ((G) - 1) & 1)                                        \
        ING(G, 0) ING(G, 1) ING(G, 2) ING(G, 3) }
    GBODY(1) GBODY(2) GBODY(3) GBODY(4) GBODY(5)
    GBODY(6) GBODY(7) GBODY(8) GBODY(9) GBODY(10)
#undef GBODY

    __syncthreads();
    HSTEP(10, 0)

#undef HSTEP
#undef ING
#undef LOADS
#undef VBUF

    // ── block reduction: warp shuffles, then serial over 16 warps ──
    float v = lsum;
#pragma unroll
    for (int off = 16; off; off >>= 1)
        v += __shfl_xor_sync(0xFFFFFFFFu, v, off);
    if ((c & 31) == 0) red[c >> 5] = v;
    __syncthreads();

    if (c == 0) {
        float bs = 0.f;
#pragma unroll
        for (int w = 0; w < 16; ++w) bs += red[w];
        g_part[plane * NBANDS + band] = bs;
        __threadfence();
        const unsigned t = atomicAdd(&g_count, 1u);
        amLast = (t == NBLK - 1);
    }
    __syncthreads();

    // ── last block performs the final (deterministic) reduction ──
    if (amLast) {
        __threadfence();
        double s = 0.0;
        for (int i = c; i < NBLK; i += 512) s += (double)g_part[i];
        sd[c] = s;
        __syncthreads();
#pragma unroll
        for (int k = 256; k > 0; k >>= 1) {
            if (c < k) sd[c] += sd[c + k];
            __syncthreads();
        }
        if (c == 0) {
            out[0]  = (float)(1.0 - sd[0] / 25165824.0);  // 32*3*512*512
            g_count = 0;                                   // reset for replay
        }
    }
}

extern "C" void kernel_launch(void* const* d_in, const int* in_sizes, int n_in,
                              void* d_out, int out_size)
{
    (void)in_sizes; (void)n_in; (void)out_size;
    const float* img1 = (const float*)d_in[0];
    const float* img2 = (const float*)d_in[1];
    cudaFuncSetAttribute(ssim_main, cudaFuncAttributeMaxDynamicSharedMemorySize,
                         SMEM_DYN);
    dim3 grid(NBANDS, NPLANES);
    ssim_main<<<grid, 512, SMEM_DYN>>>(img1, img2, (float*)d_out);
}